// round 4
// baseline (speedup 1.0000x reference)
#include <cuda_runtime.h>

// DWT2 (2x2 Haar) : x[16,64,256,256] f32 -> out[16,256,128,128] f32
//   out[n, i*64+c, y, x] from 2x2 block at x[n,c,2y:2y+2, 2x:2x+2]
// HAAR rows: i0:(+ + + +), i1:(+ + - -), i2:(+ - + -), i3:(+ - - +), all * 0.5

static constexpr int N  = 16;
static constexpr int C  = 64;
static constexpr int H  = 256;
static constexpr int W  = 256;
static constexpr int H2 = H / 2;   // 128
static constexpr int W2 = W / 2;   // 128

// Each thread: 8 input columns x 2 rows (4x float4 loads = 64B) -> 4 output px
// per band (float4 stores = 64B total out).
static constexpr int XGROUPS = W / 8;                 // 32 groups along W
static constexpr long long TOTAL = (long long)N * C * H2 * XGROUPS;  // 4,194,304
static constexpr int PLANE = H2 * W2;                 // 16384
static constexpr int OUT_I_STRIDE = C * PLANE;        // 1,048,576 floats between bands

__global__ __launch_bounds__(256) void dwt2_haar_kernel(
    const float* __restrict__ x, float* __restrict__ out)
{
    long long idx = (long long)blockIdx.x * blockDim.x + threadIdx.x;
    if (idx >= TOTAL) return;

    int xg = (int)(idx % XGROUPS);              // 8-column group along W
    int y  = (int)((idx / XGROUPS) % H2);       // output row
    int c  = (int)((idx / ((long long)XGROUPS * H2)) % C);
    int n  = (int)( idx / ((long long)XGROUPS * H2 * C));

    const float* row0 = x + (((long long)(n * C + c) * H + 2 * y) * W + 8 * xg);
    const float* row1 = row0 + W;

    // 4 independent 128-bit streaming loads (MLP=4, evict-first)
    float4 r0a = __ldcs(reinterpret_cast<const float4*>(row0));
    float4 r0b = __ldcs(reinterpret_cast<const float4*>(row0 + 4));
    float4 r1a = __ldcs(reinterpret_cast<const float4*>(row1));
    float4 r1b = __ldcs(reinterpret_cast<const float4*>(row1 + 4));

    // 4 output pixels; pixel k has (a,b) from row0, (c,d) from row1
    float a[4] = { r0a.x, r0a.z, r0b.x, r0b.z };
    float b[4] = { r0a.y, r0a.w, r0b.y, r0b.w };
    float cc[4] = { r1a.x, r1a.z, r1b.x, r1b.z };
    float d[4] = { r1a.y, r1a.w, r1b.y, r1b.w };

    float4 o0, o1, o2, o3;
    float* p0 = &o0.x; float* p1 = &o1.x; float* p2 = &o2.x; float* p3 = &o3.x;
    #pragma unroll
    for (int k = 0; k < 4; k++) {
        float abp = a[k] + b[k], abm = a[k] - b[k];
        float cdp = cc[k] + d[k], cdm = cc[k] - d[k];
        p0[k] = 0.5f * (abp + cdp);   // LL
        p1[k] = 0.5f * (abp - cdp);
        p2[k] = 0.5f * (abm + cdm);
        p3[k] = 0.5f * (abm - cdm);
    }

    // out[n, i*C + c, y, 4*xg .. 4*xg+3] — full float4 streaming stores
    long long obase = ((long long)n * 4 * C + c) * PLANE + (long long)y * W2 + 4 * xg;
    float* o = out + obase;
    __stcs(reinterpret_cast<float4*>(o),                    o0);
    __stcs(reinterpret_cast<float4*>(o + 1 * OUT_I_STRIDE), o1);
    __stcs(reinterpret_cast<float4*>(o + 2 * OUT_I_STRIDE), o2);
    __stcs(reinterpret_cast<float4*>(o + 3 * OUT_I_STRIDE), o3);
}

extern "C" void kernel_launch(void* const* d_in, const int* in_sizes, int n_in,
                              void* d_out, int out_size)
{
    const float* x = (const float*)d_in[0];
    float* out = (float*)d_out;

    const int threads = 256;
    const long long blocks = (TOTAL + threads - 1) / threads;  // 16384
    dwt2_haar_kernel<<<(unsigned)blocks, threads>>>(x, out);
}

// round 5
// speedup vs baseline: 1.0211x; 1.0211x over previous
#include <cuda_runtime.h>

// DWT2 (2x2 Haar) : x[16,64,256,256] f32 -> out[16,256,128,128] f32
//   out[n, i*64+c, y, x] from 2x2 block at x[n,c,2y:2y+2, 2x:2x+2]
// HAAR rows: i0:(+ + + +), i1:(+ + - -), i2:(+ - + -), i3:(+ - - +), all * 0.5
//
// R1 shape (best): per-thread = 2x float4 loads (rows 2y,2y+1), 4x float2 stores.
// R4 delta: streaming cache hints only (__ldcs/__stcs).

static constexpr int N  = 16;
static constexpr int C  = 64;
static constexpr int H  = 256;
static constexpr int W  = 256;
static constexpr int H2 = H / 2;   // 128
static constexpr int W2 = W / 2;   // 128

static constexpr int XGROUPS = W / 4;                 // 64
static constexpr long long TOTAL = (long long)N * C * H2 * XGROUPS;  // 8,388,608
static constexpr int PLANE = H2 * W2;                 // 16384
static constexpr int OUT_I_STRIDE = C * PLANE;        // 1,048,576

__global__ __launch_bounds__(256) void dwt2_haar_kernel(
    const float* __restrict__ x, float* __restrict__ out)
{
    long long idx = (long long)blockIdx.x * blockDim.x + threadIdx.x;
    if (idx >= TOTAL) return;

    int xg = (int)(idx % XGROUPS);              // float4 group along W
    int y  = (int)((idx / XGROUPS) % H2);       // output row
    int c  = (int)((idx / ((long long)XGROUPS * H2)) % C);
    int n  = (int)( idx / ((long long)XGROUPS * H2 * C));

    const float* row0 = x + (((long long)(n * C + c) * H + 2 * y) * W + 4 * xg);
    const float* row1 = row0 + W;

    float4 r0 = __ldcs(reinterpret_cast<const float4*>(row0));
    float4 r1 = __ldcs(reinterpret_cast<const float4*>(row1));

    float a0 = r0.x, b0 = r0.y, a1 = r0.z, b1 = r0.w;
    float c0 = r1.x, d0 = r1.y, c1 = r1.z, d1 = r1.w;

    float ab0p = a0 + b0, ab0m = a0 - b0;
    float cd0p = c0 + d0, cd0m = c0 - d0;
    float ab1p = a1 + b1, ab1m = a1 - b1;
    float cd1p = c1 + d1, cd1m = c1 - d1;

    float2 o0 = make_float2(0.5f * (ab0p + cd0p), 0.5f * (ab1p + cd1p)); // LL
    float2 o1 = make_float2(0.5f * (ab0p - cd0p), 0.5f * (ab1p - cd1p));
    float2 o2 = make_float2(0.5f * (ab0m + cd0m), 0.5f * (ab1m + cd1m));
    float2 o3 = make_float2(0.5f * (ab0m - cd0m), 0.5f * (ab1m - cd1m));

    long long obase = ((long long)n * 4 * C + c) * PLANE + (long long)y * W2 + 2 * xg;
    float* o = out + obase;
    __stcs(reinterpret_cast<float2*>(o),                    o0);
    __stcs(reinterpret_cast<float2*>(o + 1 * OUT_I_STRIDE), o1);
    __stcs(reinterpret_cast<float2*>(o + 2 * OUT_I_STRIDE), o2);
    __stcs(reinterpret_cast<float2*>(o + 3 * OUT_I_STRIDE), o3);
}

extern "C" void kernel_launch(void* const* d_in, const int* in_sizes, int n_in,
                              void* d_out, int out_size)
{
    const float* x = (const float*)d_in[0];
    float* out = (float*)d_out;

    const int threads = 256;
    const long long blocks = (TOTAL + threads - 1) / threads;  // 32768
    dwt2_haar_kernel<<<(unsigned)blocks, threads>>>(x, out);
}